// round 8
// baseline (speedup 1.0000x reference)
#include <cuda_runtime.h>

// 2-layer LSTM (IN=16, H=32, T=512, B=4096) + MLP head, fully fused.
// R8: unit-split warp pairs. A pair of warps shares 8 sequences; warp r owns
// hidden units [16r, 16r+16). Lane = (seq-half sg = lane>>4, unit ul = lane&15).
//  - Weight LDS.128: 16 distinct addresses/warp (sg halves broadcast) -> 2
//    wavefronts serving 8 sequences (R7: 4 wf serving 4) => weight traffic /4.
//  - Activations staged in padded smem (stride 36/20 floats) so the two sg
//    halves hit disjoint banks -> 1 wavefront broadcast loads.
//  - One 64-thread named barrier per timestep; h0/h1/x double-buffered by t&1.
//  - Gate math: fma.rn.f32x2 over j-pairs (zero packing MOVs), 16 u64 accums.
// New floor: FMA pipe, 2 warps/SMSP x 896 FFMA2 x 2cyc = 3584 cyc/step ~ 0.97ms.

#define FULLMASK 0xffffffffu

constexpr int T_LEN = 512;
constexpr int IN_DIM = 16;
constexpr int H_DIM = 32;
constexpr int SEQ_PER_PAIR = 8;
constexpr int PAIRS_PER_BLOCK = 4;
constexpr int WARPS_PER_BLOCK = 8;
constexpr int THREADS = WARPS_PER_BLOCK * 32;
constexpr int H_STRIDE = 36;  // floats; 4 rows = 144 ≡ 16 (mod 32) banks, 16B-aligned
constexpr int X_STRIDE = 20;  // floats; 4 rows = 80  ≡ 16 (mod 32) banks, 16B-aligned

// Weight arrays: [jp][unit] float4.
//  A = (wi[2jp], wi[2jp+1], wf[2jp], wf[2jp+1])
//  B = (wg[2jp], wg[2jp+1], wo[2jp], wo[2jp+1])
struct SmemW {
    float4 ihA0[IN_DIM / 2][H_DIM];
    float4 ihB0[IN_DIM / 2][H_DIM];
    float4 hhA0[H_DIM / 2][H_DIM];
    float4 hhB0[H_DIM / 2][H_DIM];
    float4 ihA1[H_DIM / 2][H_DIM];
    float4 ihB1[H_DIM / 2][H_DIM];
    float4 hhA1[H_DIM / 2][H_DIM];
    float4 hhB1[H_DIM / 2][H_DIM];
    float4 bg0[H_DIM];
    float4 bg1[H_DIM];
};

// Per-pair double-buffered activation staging.
struct __align__(16) Stage {
    float h0[2][SEQ_PER_PAIR][H_STRIDE];
    float h1[2][SEQ_PER_PAIR][H_STRIDE];
    float x[2][SEQ_PER_PAIR][X_STRIDE];
};

struct SmemAll {
    SmemW w;
    Stage st[PAIRS_PER_BLOCK];
};

typedef unsigned long long u64;

__device__ __forceinline__ u64 fma2(u64 a, u64 b, u64 c) {
    u64 d;
    asm("fma.rn.f32x2 %0, %1, %2, %3;" : "=l"(d) : "l"(a), "l"(b), "l"(c));
    return d;
}
__device__ __forceinline__ u64 pack2f(float a, float b) {
    u64 r;
    asm("mov.b64 %0, {%1, %2};" : "=l"(r) : "f"(a), "f"(b));
    return r;
}
__device__ __forceinline__ float2 unpack2(u64 v) {
    float2 r;
    asm("mov.b64 {%0, %1}, %2;" : "=f"(r.x), "=f"(r.y) : "l"(v));
    return r;
}
__device__ __forceinline__ float hsum2(u64 v) {
    float2 r = unpack2(v);
    return r.x + r.y;
}

__device__ __forceinline__ float fast_sigmoid(float x) {
    return __fdividef(1.0f, 1.0f + __expf(-x));
}
__device__ __forceinline__ float fast_tanh(float x) {
    float a = fabsf(x);
    float e = __expf(-2.0f * a);
    float r = __fdividef(1.0f - e, 1.0f + e);
    return copysignf(r, x);
}

__device__ __forceinline__ void pair_bar(int pair) {
    asm volatile("bar.sync %0, %1;" :: "r"(pair + 1), "r"(64) : "memory");
}

__global__ void __launch_bounds__(THREADS, 1)
lstm_fused_kernel(const float* __restrict__ x,
                  const float* __restrict__ Wih0, const float* __restrict__ Whh0,
                  const float* __restrict__ bih0, const float* __restrict__ bhh0,
                  const float* __restrict__ Wih1, const float* __restrict__ Whh1,
                  const float* __restrict__ bih1, const float* __restrict__ bhh1,
                  const float* __restrict__ W1, const float* __restrict__ b1,
                  const float* __restrict__ W2, const float* __restrict__ b2,
                  float* __restrict__ out, int batch) {
    extern __shared__ char smem_raw[];
    SmemAll* sm = reinterpret_cast<SmemAll*>(smem_raw);
    SmemW* s = &sm->w;

    const int tid = threadIdx.x;

    // ---- Stage weights as gate j-pairs (block cooperative) ----
    for (int i = tid; i < (IN_DIM / 2) * H_DIM; i += THREADS) {
        int jp = i / H_DIM, u = i % H_DIM;
        int j0 = 2 * jp, j1 = 2 * jp + 1;
        s->ihA0[jp][u] = make_float4(Wih0[(0 * H_DIM + u) * IN_DIM + j0],
                                     Wih0[(0 * H_DIM + u) * IN_DIM + j1],
                                     Wih0[(1 * H_DIM + u) * IN_DIM + j0],
                                     Wih0[(1 * H_DIM + u) * IN_DIM + j1]);
        s->ihB0[jp][u] = make_float4(Wih0[(2 * H_DIM + u) * IN_DIM + j0],
                                     Wih0[(2 * H_DIM + u) * IN_DIM + j1],
                                     Wih0[(3 * H_DIM + u) * IN_DIM + j0],
                                     Wih0[(3 * H_DIM + u) * IN_DIM + j1]);
    }
    for (int i = tid; i < (H_DIM / 2) * H_DIM; i += THREADS) {
        int jp = i / H_DIM, u = i % H_DIM;
        int j0 = 2 * jp, j1 = 2 * jp + 1;
        s->hhA0[jp][u] = make_float4(Whh0[(0 * H_DIM + u) * H_DIM + j0],
                                     Whh0[(0 * H_DIM + u) * H_DIM + j1],
                                     Whh0[(1 * H_DIM + u) * H_DIM + j0],
                                     Whh0[(1 * H_DIM + u) * H_DIM + j1]);
        s->hhB0[jp][u] = make_float4(Whh0[(2 * H_DIM + u) * H_DIM + j0],
                                     Whh0[(2 * H_DIM + u) * H_DIM + j1],
                                     Whh0[(3 * H_DIM + u) * H_DIM + j0],
                                     Whh0[(3 * H_DIM + u) * H_DIM + j1]);
        s->ihA1[jp][u] = make_float4(Wih1[(0 * H_DIM + u) * H_DIM + j0],
                                     Wih1[(0 * H_DIM + u) * H_DIM + j1],
                                     Wih1[(1 * H_DIM + u) * H_DIM + j0],
                                     Wih1[(1 * H_DIM + u) * H_DIM + j1]);
        s->ihB1[jp][u] = make_float4(Wih1[(2 * H_DIM + u) * H_DIM + j0],
                                     Wih1[(2 * H_DIM + u) * H_DIM + j1],
                                     Wih1[(3 * H_DIM + u) * H_DIM + j0],
                                     Wih1[(3 * H_DIM + u) * H_DIM + j1]);
        s->hhA1[jp][u] = make_float4(Whh1[(0 * H_DIM + u) * H_DIM + j0],
                                     Whh1[(0 * H_DIM + u) * H_DIM + j1],
                                     Whh1[(1 * H_DIM + u) * H_DIM + j0],
                                     Whh1[(1 * H_DIM + u) * H_DIM + j1]);
        s->hhB1[jp][u] = make_float4(Whh1[(2 * H_DIM + u) * H_DIM + j0],
                                     Whh1[(2 * H_DIM + u) * H_DIM + j1],
                                     Whh1[(3 * H_DIM + u) * H_DIM + j0],
                                     Whh1[(3 * H_DIM + u) * H_DIM + j1]);
    }
    for (int u = tid; u < H_DIM; u += THREADS) {
        s->bg0[u] = make_float4(bih0[0 * H_DIM + u] + bhh0[0 * H_DIM + u],
                                bih0[1 * H_DIM + u] + bhh0[1 * H_DIM + u],
                                bih0[2 * H_DIM + u] + bhh0[2 * H_DIM + u],
                                bih0[3 * H_DIM + u] + bhh0[3 * H_DIM + u]);
        s->bg1[u] = make_float4(bih1[0 * H_DIM + u] + bhh1[0 * H_DIM + u],
                                bih1[1 * H_DIM + u] + bhh1[1 * H_DIM + u],
                                bih1[2 * H_DIM + u] + bhh1[2 * H_DIM + u],
                                bih1[3 * H_DIM + u] + bhh1[3 * H_DIM + u]);
    }

    const int warp = tid >> 5;
    const int lane = tid & 31;
    const int pair = warp >> 1;        // 0..3
    const int r = warp & 1;            // unit half
    const int sg = lane >> 4;          // seq half (0: seqs 0-3, 1: seqs 4-7)
    const int ul = lane & 15;
    const int unit = r * 16 + ul;      // this lane's hidden unit
    const int sg4 = sg * 4;
    Stage* st = &sm->st[pair];
    const int seq_base = (blockIdx.x * PAIRS_PER_BLOCK + pair) * SEQ_PER_PAIR;

    // Init staging (before block sync).
    const size_t seq_stride = (size_t)T_LEN * IN_DIM;
    const int xls = r * 4 + (lane >> 2);   // seq index (0..7) this lane loads x for
    const int xq = lane & 3;               // quarter of the 16 dims
    const float* xload = x + (size_t)(seq_base + xls) * seq_stride + 4 * xq;
    if (seq_base < batch) {
#pragma unroll
        for (int ss = 0; ss < 4; ss++) {
            st->h0[0][sg4 + ss][unit] = 0.f;
            st->h1[0][sg4 + ss][unit] = 0.f;
        }
        if (lane < 16)
            *reinterpret_cast<float4*>(&st->x[0][xls][4 * xq]) =
                *reinterpret_cast<const float4*>(xload);
    }
    __syncthreads();
    if (seq_base >= batch) return;  // whole pair exits together

    // Biases packed (lo = bias, hi = 0) for this lane's unit.
    const float4 b0v = s->bg0[unit];
    const float4 b1v = s->bg1[unit];
    const u64 bi0 = pack2f(b0v.x, 0.f), bf0 = pack2f(b0v.y, 0.f);
    const u64 bg0_ = pack2f(b0v.z, 0.f), bo0 = pack2f(b0v.w, 0.f);
    const u64 bi1 = pack2f(b1v.x, 0.f), bf1 = pack2f(b1v.y, 0.f);
    const u64 bg1_ = pack2f(b1v.z, 0.f), bo1 = pack2f(b1v.w, 0.f);

    float c0f[4] = {0, 0, 0, 0};
    float c1f[4] = {0, 0, 0, 0};

    for (int t = 0; t < T_LEN; t++) {
        const int buf = t & 1;      // read buffer
        const int nbuf = buf ^ 1;   // write buffer

        // Prefetch x(t+1).
        float4 xn = make_float4(0.f, 0.f, 0.f, 0.f);
        if (t + 1 < T_LEN && lane < 16)
            xn = *reinterpret_cast<const float4*>(xload + (t + 1) * IN_DIM);

        u64 ai[4], af[4], ag[4], ao[4];

        // ===== Layer 0: ih0 (x), bias folded into group 0 =====
#pragma unroll
        for (int g = 0; g < IN_DIM / 4; g++) {
            ulonglong2 A0 = *reinterpret_cast<const ulonglong2*>(&s->ihA0[2 * g][unit]);
            ulonglong2 B0 = *reinterpret_cast<const ulonglong2*>(&s->ihB0[2 * g][unit]);
            ulonglong2 A1 = *reinterpret_cast<const ulonglong2*>(&s->ihA0[2 * g + 1][unit]);
            ulonglong2 B1 = *reinterpret_cast<const ulonglong2*>(&s->ihB0[2 * g + 1][unit]);
#pragma unroll
            for (int ss = 0; ss < 4; ss++) {
                ulonglong2 xv =
                    *reinterpret_cast<const ulonglong2*>(&st->x[buf][sg4 + ss][4 * g]);
                if (g == 0) {
                    ai[ss] = fma2(A0.x, xv.x, bi0);
                    af[ss] = fma2(A0.y, xv.x, bf0);
                    ag[ss] = fma2(B0.x, xv.x, bg0_);
                    ao[ss] = fma2(B0.y, xv.x, bo0);
                } else {
                    ai[ss] = fma2(A0.x, xv.x, ai[ss]);
                    af[ss] = fma2(A0.y, xv.x, af[ss]);
                    ag[ss] = fma2(B0.x, xv.x, ag[ss]);
                    ao[ss] = fma2(B0.y, xv.x, ao[ss]);
                }
                ai[ss] = fma2(A1.x, xv.y, ai[ss]);
                af[ss] = fma2(A1.y, xv.y, af[ss]);
                ag[ss] = fma2(B1.x, xv.y, ag[ss]);
                ao[ss] = fma2(B1.y, xv.y, ao[ss]);
            }
        }
        // ===== Layer 0: hh0 (h0 prev) =====
#pragma unroll
        for (int g = 0; g < H_DIM / 4; g++) {
            ulonglong2 A0 = *reinterpret_cast<const ulonglong2*>(&s->hhA0[2 * g][unit]);
            ulonglong2 B0 = *reinterpret_cast<const ulonglong2*>(&s->hhB0[2 * g][unit]);
            ulonglong2 A1 = *reinterpret_cast<const ulonglong2*>(&s->hhA0[2 * g + 1][unit]);
            ulonglong2 B1 = *reinterpret_cast<const ulonglong2*>(&s->hhB0[2 * g + 1][unit]);
#pragma unroll
            for (int ss = 0; ss < 4; ss++) {
                ulonglong2 hv =
                    *reinterpret_cast<const ulonglong2*>(&st->h0[buf][sg4 + ss][4 * g]);
                ai[ss] = fma2(A0.x, hv.x, ai[ss]);
                af[ss] = fma2(A0.y, hv.x, af[ss]);
                ag[ss] = fma2(B0.x, hv.x, ag[ss]);
                ao[ss] = fma2(B0.y, hv.x, ao[ss]);
                ai[ss] = fma2(A1.x, hv.y, ai[ss]);
                af[ss] = fma2(A1.y, hv.y, af[ss]);
                ag[ss] = fma2(B1.x, hv.y, ag[ss]);
                ao[ss] = fma2(B1.y, hv.y, ao[ss]);
            }
        }
        // ===== Cell 0: stage h0(t) into nbuf =====
#pragma unroll
        for (int ss = 0; ss < 4; ss++) {
            float ig = fast_sigmoid(hsum2(ai[ss]));
            float fg = fast_sigmoid(hsum2(af[ss]));
            float gg = fast_tanh(hsum2(ag[ss]));
            float og = fast_sigmoid(hsum2(ao[ss]));
            c0f[ss] = fmaf(fg, c0f[ss], ig * gg);
            st->h0[nbuf][sg4 + ss][unit] = og * fast_tanh(c0f[ss]);
        }
        // Stage x(t+1) into nbuf (x(t-1) readers finished before bar(t-1)).
        if (lane < 16)
            *reinterpret_cast<float4*>(&st->x[nbuf][xls][4 * xq]) = xn;

        pair_bar(pair);  // h0(t) + x(t+1) visible to both warps of the pair

        // ===== Layer 1: hh1 first (h1(t-1) in buf; independent of h0(t)) =====
#pragma unroll
        for (int g = 0; g < H_DIM / 4; g++) {
            ulonglong2 A0 = *reinterpret_cast<const ulonglong2*>(&s->hhA1[2 * g][unit]);
            ulonglong2 B0 = *reinterpret_cast<const ulonglong2*>(&s->hhB1[2 * g][unit]);
            ulonglong2 A1 = *reinterpret_cast<const ulonglong2*>(&s->hhA1[2 * g + 1][unit]);
            ulonglong2 B1 = *reinterpret_cast<const ulonglong2*>(&s->hhB1[2 * g + 1][unit]);
#pragma unroll
            for (int ss = 0; ss < 4; ss++) {
                ulonglong2 hv =
                    *reinterpret_cast<const ulonglong2*>(&st->h1[buf][sg4 + ss][4 * g]);
                if (g == 0) {
                    ai[ss] = fma2(A0.x, hv.x, bi1);
                    af[ss] = fma2(A0.y, hv.x, bf1);
                    ag[ss] = fma2(B0.x, hv.x, bg1_);
                    ao[ss] = fma2(B0.y, hv.x, bo1);
                } else {
                    ai[ss] = fma2(A0.x, hv.x, ai[ss]);
                    af[ss] = fma2(A0.y, hv.x, af[ss]);
                    ag[ss] = fma2(B0.x, hv.x, ag[ss]);
                    ao[ss] = fma2(B0.y, hv.x, ao[ss]);
                }
                ai[ss] = fma2(A1.x, hv.y, ai[ss]);
                af[ss] = fma2(A1.y, hv.y, af[ss]);
                ag[ss] = fma2(B1.x, hv.y, ag[ss]);
                ao[ss] = fma2(B1.y, hv.y, ao[ss]);
            }
        }
        // ===== Layer 1: ih1 (h0(t), staged in nbuf) =====
#pragma unroll
        for (int g = 0; g < H_DIM / 4; g++) {
            ulonglong2 A0 = *reinterpret_cast<const ulonglong2*>(&s->ihA1[2 * g][unit]);
            ulonglong2 B0 = *reinterpret_cast<const ulonglong2*>(&s->ihB1[2 * g][unit]);
            ulonglong2 A1 = *reinterpret_cast<const ulonglong2*>(&s->ihA1[2 * g + 1][unit]);
            ulonglong2 B1 = *reinterpret_cast<const ulonglong2*>(&s->ihB1[2 * g + 1][unit]);
#pragma unroll
            for (int ss = 0; ss < 4; ss++) {
                ulonglong2 hv =
                    *reinterpret_cast<const ulonglong2*>(&st->h0[nbuf][sg4 + ss][4 * g]);
                ai[ss] = fma2(A0.x, hv.x, ai[ss]);
                af[ss] = fma2(A0.y, hv.x, af[ss]);
                ag[ss] = fma2(B0.x, hv.x, ag[ss]);
                ao[ss] = fma2(B0.y, hv.x, ao[ss]);
                ai[ss] = fma2(A1.x, hv.y, ai[ss]);
                af[ss] = fma2(A1.y, hv.y, af[ss]);
                ag[ss] = fma2(B1.x, hv.y, ag[ss]);
                ao[ss] = fma2(B1.y, hv.y, ao[ss]);
            }
        }
        // ===== Cell 1: stage h1(t) into nbuf (readers ordered by bar(t+1)) =====
#pragma unroll
        for (int ss = 0; ss < 4; ss++) {
            float ig = fast_sigmoid(hsum2(ai[ss]));
            float fg = fast_sigmoid(hsum2(af[ss]));
            float gg = fast_tanh(hsum2(ag[ss]));
            float og = fast_sigmoid(hsum2(ao[ss]));
            c1f[ss] = fmaf(fg, c1f[ss], ig * gg);
            st->h1[nbuf][sg4 + ss][unit] = og * fast_tanh(c1f[ss]);
        }
    }

    pair_bar(pair);  // final h1 stores visible

    // ---- Head: z = relu(h1 @ W1.T + b1); y = z @ W2.T + b2 ----
    // Warp r handles the pair's seqs [4r, 4r+4); final h1 lives in buffer 0.
    float bias2 = __ldg(b2);
    float bm = (lane < 16) ? __ldg(b1 + lane) : 0.f;
    float w2m = (lane < 16) ? __ldg(W2 + lane) : 0.f;
#pragma unroll
    for (int ss = 0; ss < 4; ss++) {
        int srow = r * 4 + ss;
        float z = bm;
#pragma unroll
        for (int j = 0; j < H_DIM; j++) {
            float wm = (lane < 16) ? __ldg(W1 + lane * H_DIM + j) : 0.f;
            z = fmaf(wm, st->h1[0][srow][j], z);
        }
        float v = fmaxf(z, 0.f) * w2m;
#pragma unroll
        for (int off = 8; off >= 1; off >>= 1)
            v += __shfl_xor_sync(FULLMASK, v, off, 16);
        if (lane == 0) out[seq_base + srow] = v + bias2;
    }
}

extern "C" void kernel_launch(void* const* d_in, const int* in_sizes, int n_in,
                              void* d_out, int out_size) {
    const float* x    = (const float*)d_in[0];
    const float* Wih0 = (const float*)d_in[1];
    const float* Whh0 = (const float*)d_in[2];
    const float* bih0 = (const float*)d_in[3];
    const float* bhh0 = (const float*)d_in[4];
    const float* Wih1 = (const float*)d_in[5];
    const float* Whh1 = (const float*)d_in[6];
    const float* bih1 = (const float*)d_in[7];
    const float* bhh1 = (const float*)d_in[8];
    const float* W1   = (const float*)d_in[9];
    const float* b1   = (const float*)d_in[10];
    const float* W2   = (const float*)d_in[11];
    const float* b2   = (const float*)d_in[12];
    float* out = (float*)d_out;

    int batch = in_sizes[0] / (T_LEN * IN_DIM);  // 4096

    cudaFuncSetAttribute(lstm_fused_kernel,
                         cudaFuncAttributeMaxDynamicSharedMemorySize,
                         (int)sizeof(SmemAll));

    int pairs = (batch + SEQ_PER_PAIR - 1) / SEQ_PER_PAIR;              // 512
    int blocks = (pairs + PAIRS_PER_BLOCK - 1) / PAIRS_PER_BLOCK;       // 128
    lstm_fused_kernel<<<blocks, THREADS, sizeof(SmemAll)>>>(
        x, Wih0, Whh0, bih0, bhh0, Wih1, Whh1, bih1, bhh1,
        W1, b1, W2, b2, out, batch);
}

// round 9
// speedup vs baseline: 1.0436x; 1.0436x over previous
#include <cuda_runtime.h>

// 2-layer LSTM (IN=16, H=32, T=512, B=4096) + MLP head, fully fused.
// R9: LAYER-SPLIT warp pairs at S=8. Warp A = layer 0 only, warp B = layer 1
// only, sharing 8 sequences via smem staging + one 64-thread named barrier per
// timestep. Each warp ingests only its layer's weights (the LSU cost is
// lane-delivery-based -- R8 measurement), so per-seq weight traffic halves vs
// R7 while total warps stay 1024 (8/SM). Accumulators are SEQ-PAIR packed
// f32x2 (bias folds into both halves, no final hsum); weight scalars are
// duplicated with mov.b64 (idle ALU pipe). role = warp>>2 puts one A and one
// B warp on every SMSP (balanced FMA). Floor: FMA 3584 cyc/SMSP-step ~ 966us.

#define FULLMASK 0xffffffffu
typedef unsigned long long u64;

constexpr int T_LEN = 512;
constexpr int IN_DIM = 16;
constexpr int H_DIM = 32;
constexpr int SEQ_PER_PAIR = 8;
constexpr int PAIRS_PER_BLOCK = 4;
constexpr int THREADS = 256;          // 8 warps: 0-3 = L0 of pair w, 4-7 = L1
constexpr int HROW = 34;              // u64 row stride (272B = 17*16, aligned)
constexpr int XROW = 18;              // u64 row stride (144B = 9*16, aligned)

// Weights: [j][unit] float4 = (wi,wf,wg,wo) for input dim j, hidden unit u.
struct SmemW {
    float4 wih0[IN_DIM][H_DIM];
    float4 whh0[H_DIM][H_DIM];
    float4 wih1[H_DIM][H_DIM];
    float4 whh1[H_DIM][H_DIM];
    float4 bg0[H_DIM];   // (bi,bf,bg,bo) per unit (bih+bhh)
    float4 bg1[H_DIM];
};

// Per-pair staging. h*/x rows: [seq-pair sp][unit/dim as u64 = (val_s0,val_s1)]
struct __align__(16) Stage {
    u64 h0[2][4][HROW];   // double-buffered, written by L0, read by both
    u64 h1[2][4][HROW];   // L1-private
    u64 x[2][4][XROW];    // L0-private
};

struct SmemAll {
    SmemW w;
    Stage st[PAIRS_PER_BLOCK];
};

__device__ __forceinline__ u64 fma2(u64 a, u64 b, u64 c) {
    u64 d;
    asm("fma.rn.f32x2 %0, %1, %2, %3;" : "=l"(d) : "l"(a), "l"(b), "l"(c));
    return d;
}
__device__ __forceinline__ u64 pack2(float v) {
    u64 r;
    asm("mov.b64 %0, {%1, %1};" : "=l"(r) : "f"(v));
    return r;
}
__device__ __forceinline__ u64 pack2f(float a, float b) {
    u64 r;
    asm("mov.b64 %0, {%1, %2};" : "=l"(r) : "f"(a), "f"(b));
    return r;
}
__device__ __forceinline__ float2 unpack2(u64 v) {
    float2 r;
    asm("mov.b64 {%0, %1}, %2;" : "=f"(r.x), "=f"(r.y) : "l"(v));
    return r;
}

__device__ __forceinline__ float fast_sigmoid(float x) {
    return __fdividef(1.0f, 1.0f + __expf(-x));
}
__device__ __forceinline__ float fast_tanh(float x) {
    float a = fabsf(x);
    float e = __expf(-2.0f * a);
    float r = __fdividef(1.0f - e, 1.0f + e);
    return copysignf(r, x);
}

__device__ __forceinline__ void pair_bar(int pair) {
    asm volatile("bar.sync %0, %1;" :: "r"(pair + 1), "r"(64) : "memory");
}

// One j-pair contribution: weights quads w0 (j=2jp), w1 (j=2jp+1); act = two
// seq-pair-packed u64 per sp. 8 FFMA2 per sp.
#define JP_STEP(W0, W1, ACTP)                                              \
    do {                                                                   \
        u64 wi0 = pack2((W0).x), wf0 = pack2((W0).y);                      \
        u64 wg0 = pack2((W0).z), wo0 = pack2((W0).w);                      \
        u64 wi1 = pack2((W1).x), wf1 = pack2((W1).y);                      \
        u64 wg1 = pack2((W1).z), wo1 = pack2((W1).w);                      \
        _Pragma("unroll")                                                  \
        for (int sp = 0; sp < 4; sp++) {                                   \
            ulonglong2 a = *reinterpret_cast<const ulonglong2*>(ACTP(sp)); \
            ai[sp] = fma2(wi0, a.x, ai[sp]);                               \
            af[sp] = fma2(wf0, a.x, af[sp]);                               \
            ag[sp] = fma2(wg0, a.x, ag[sp]);                               \
            ao[sp] = fma2(wo0, a.x, ao[sp]);                               \
            ai[sp] = fma2(wi1, a.y, ai[sp]);                               \
            af[sp] = fma2(wf1, a.y, af[sp]);                               \
            ag[sp] = fma2(wg1, a.y, ag[sp]);                               \
            ao[sp] = fma2(wo1, a.y, ao[sp]);                               \
        }                                                                  \
    } while (0)

__global__ void __launch_bounds__(THREADS, 1)
lstm_fused_kernel(const float* __restrict__ x,
                  const float* __restrict__ Wih0, const float* __restrict__ Whh0,
                  const float* __restrict__ bih0, const float* __restrict__ bhh0,
                  const float* __restrict__ Wih1, const float* __restrict__ Whh1,
                  const float* __restrict__ bih1, const float* __restrict__ bhh1,
                  const float* __restrict__ W1, const float* __restrict__ b1,
                  const float* __restrict__ W2, const float* __restrict__ b2,
                  float* __restrict__ out, int batch) {
    extern __shared__ char smem_raw[];
    SmemAll* sm = reinterpret_cast<SmemAll*>(smem_raw);
    SmemW* s = &sm->w;

    const int tid = threadIdx.x;

    // ---- Stage weights as [j][unit] gate quads ----
    for (int i = tid; i < IN_DIM * H_DIM; i += THREADS) {
        int j = i / H_DIM, u = i % H_DIM;
        s->wih0[j][u] = make_float4(Wih0[(0 * H_DIM + u) * IN_DIM + j],
                                    Wih0[(1 * H_DIM + u) * IN_DIM + j],
                                    Wih0[(2 * H_DIM + u) * IN_DIM + j],
                                    Wih0[(3 * H_DIM + u) * IN_DIM + j]);
    }
    for (int i = tid; i < H_DIM * H_DIM; i += THREADS) {
        int j = i / H_DIM, u = i % H_DIM;
        s->whh0[j][u] = make_float4(Whh0[(0 * H_DIM + u) * H_DIM + j],
                                    Whh0[(1 * H_DIM + u) * H_DIM + j],
                                    Whh0[(2 * H_DIM + u) * H_DIM + j],
                                    Whh0[(3 * H_DIM + u) * H_DIM + j]);
        s->wih1[j][u] = make_float4(Wih1[(0 * H_DIM + u) * H_DIM + j],
                                    Wih1[(1 * H_DIM + u) * H_DIM + j],
                                    Wih1[(2 * H_DIM + u) * H_DIM + j],
                                    Wih1[(3 * H_DIM + u) * H_DIM + j]);
        s->whh1[j][u] = make_float4(Whh1[(0 * H_DIM + u) * H_DIM + j],
                                    Whh1[(1 * H_DIM + u) * H_DIM + j],
                                    Whh1[(2 * H_DIM + u) * H_DIM + j],
                                    Whh1[(3 * H_DIM + u) * H_DIM + j]);
    }
    for (int u = tid; u < H_DIM; u += THREADS) {
        s->bg0[u] = make_float4(bih0[0 * H_DIM + u] + bhh0[0 * H_DIM + u],
                                bih0[1 * H_DIM + u] + bhh0[1 * H_DIM + u],
                                bih0[2 * H_DIM + u] + bhh0[2 * H_DIM + u],
                                bih0[3 * H_DIM + u] + bhh0[3 * H_DIM + u]);
        s->bg1[u] = make_float4(bih1[0 * H_DIM + u] + bhh1[0 * H_DIM + u],
                                bih1[1 * H_DIM + u] + bhh1[1 * H_DIM + u],
                                bih1[2 * H_DIM + u] + bhh1[2 * H_DIM + u],
                                bih1[3 * H_DIM + u] + bhh1[3 * H_DIM + u]);
    }

    const int warp = tid >> 5;
    const int lane = tid & 31;         // lane = hidden unit
    const int pair = warp & 3;         // 0..3
    const int role = warp >> 2;        // 0 = layer-0 warp, 1 = layer-1 warp
    Stage* st = &sm->st[pair];
    const int seq_base = (blockIdx.x * PAIRS_PER_BLOCK + pair) * SEQ_PER_PAIR;

    // x loader mapping (L0 warp): lane -> (seq xs, quarter xq)
    const int xs = lane >> 2;
    const int xq = lane & 3;
    const size_t seq_stride = (size_t)T_LEN * IN_DIM;
    const float* xload = x + (size_t)(seq_base + xs) * seq_stride + 4 * xq;

    // ---- Init staging ----
    if (seq_base < batch) {
        if (role == 0) {
#pragma unroll
            for (int sp = 0; sp < 4; sp++) st->h0[0][sp][lane] = 0ull;
            float4 v = *reinterpret_cast<const float4*>(xload);
            float* fr = reinterpret_cast<float*>(st->x[0][xs >> 1]);
            int half = xs & 1;
            fr[(4 * xq + 0) * 2 + half] = v.x;
            fr[(4 * xq + 1) * 2 + half] = v.y;
            fr[(4 * xq + 2) * 2 + half] = v.z;
            fr[(4 * xq + 3) * 2 + half] = v.w;
        } else {
#pragma unroll
            for (int sp = 0; sp < 4; sp++) st->h1[0][sp][lane] = 0ull;
        }
    }
    __syncthreads();
    if (seq_base >= batch) return;  // whole pair exits together

    if (role == 0) {
        // ================= Layer-0 warp =================
        const float4 bv = s->bg0[lane];
        const u64 BI = pack2(bv.x), BF = pack2(bv.y);
        const u64 BG = pack2(bv.z), BO = pack2(bv.w);
        float c0[8] = {0, 0, 0, 0, 0, 0, 0, 0};

        for (int t = 0; t < T_LEN; t++) {
            const int buf = t & 1, nbuf = buf ^ 1;
            float4 xn = make_float4(0.f, 0.f, 0.f, 0.f);
            if (t + 1 < T_LEN)
                xn = *reinterpret_cast<const float4*>(xload + (t + 1) * IN_DIM);

            u64 ai[4], af[4], ag[4], ao[4];
#pragma unroll
            for (int sp = 0; sp < 4; sp++) {
                ai[sp] = BI; af[sp] = BF; ag[sp] = BG; ao[sp] = BO;
            }
#pragma unroll
            for (int jp = 0; jp < IN_DIM / 2; jp++) {
                float4 w0 = s->wih0[2 * jp][lane];
                float4 w1 = s->wih0[2 * jp + 1][lane];
#define ACT_X(sp) (&st->x[buf][sp][2 * jp])
                JP_STEP(w0, w1, ACT_X);
#undef ACT_X
            }
#pragma unroll
            for (int jp = 0; jp < H_DIM / 2; jp++) {
                float4 w0 = s->whh0[2 * jp][lane];
                float4 w1 = s->whh0[2 * jp + 1][lane];
#define ACT_H0(sp) (&st->h0[buf][sp][2 * jp])
                JP_STEP(w0, w1, ACT_H0);
#undef ACT_H0
            }
            // Cell 0 + stage h0(t)
#pragma unroll
            for (int sp = 0; sp < 4; sp++) {
                float2 vi = unpack2(ai[sp]), vf = unpack2(af[sp]);
                float2 vg = unpack2(ag[sp]), vo = unpack2(ao[sp]);
                float i0 = fast_sigmoid(vi.x), i1 = fast_sigmoid(vi.y);
                float f0 = fast_sigmoid(vf.x), f1 = fast_sigmoid(vf.y);
                float g0 = fast_tanh(vg.x),    g1 = fast_tanh(vg.y);
                float o0 = fast_sigmoid(vo.x), o1 = fast_sigmoid(vo.y);
                c0[2 * sp]     = fmaf(f0, c0[2 * sp],     i0 * g0);
                c0[2 * sp + 1] = fmaf(f1, c0[2 * sp + 1], i1 * g1);
                st->h0[nbuf][sp][lane] =
                    pack2f(o0 * fast_tanh(c0[2 * sp]),
                           o1 * fast_tanh(c0[2 * sp + 1]));
            }
            // Stage x(t+1)
            {
                float* fr = reinterpret_cast<float*>(st->x[nbuf][xs >> 1]);
                int half = xs & 1;
                fr[(4 * xq + 0) * 2 + half] = xn.x;
                fr[(4 * xq + 1) * 2 + half] = xn.y;
                fr[(4 * xq + 2) * 2 + half] = xn.z;
                fr[(4 * xq + 3) * 2 + half] = xn.w;
            }
            pair_bar(pair);  // h0(t) + x(t+1) visible to the L1 warp
        }
        return;  // L0 warp done
    }

    // ================= Layer-1 warp =================
    const float4 bv = s->bg1[lane];
    const u64 BI = pack2(bv.x), BF = pack2(bv.y);
    const u64 BG = pack2(bv.z), BO = pack2(bv.w);
    float c1[8] = {0, 0, 0, 0, 0, 0, 0, 0};
    float h1n[8] = {0, 0, 0, 0, 0, 0, 0, 0};

    for (int t = 0; t < T_LEN; t++) {
        const int buf = t & 1, nbuf = buf ^ 1;

        u64 ai[4], af[4], ag[4], ao[4];
#pragma unroll
        for (int sp = 0; sp < 4; sp++) {
            ai[sp] = BI; af[sp] = BF; ag[sp] = BG; ao[sp] = BO;
        }
        // hh1 first: uses own h1(t-1); independent of L0's h0(t).
#pragma unroll
        for (int jp = 0; jp < H_DIM / 2; jp++) {
            float4 w0 = s->whh1[2 * jp][lane];
            float4 w1 = s->whh1[2 * jp + 1][lane];
#define ACT_H1(sp) (&st->h1[buf][sp][2 * jp])
            JP_STEP(w0, w1, ACT_H1);
#undef ACT_H1
        }
        pair_bar(pair);  // wait for L0's h0(t) in h0[nbuf]
#pragma unroll
        for (int jp = 0; jp < H_DIM / 2; jp++) {
            float4 w0 = s->wih1[2 * jp][lane];
            float4 w1 = s->wih1[2 * jp + 1][lane];
#define ACT_H0N(sp) (&st->h0[nbuf][sp][2 * jp])
            JP_STEP(w0, w1, ACT_H0N);
#undef ACT_H0N
        }
        // Cell 1 + stage h1(t)
#pragma unroll
        for (int sp = 0; sp < 4; sp++) {
            float2 vi = unpack2(ai[sp]), vf = unpack2(af[sp]);
            float2 vg = unpack2(ag[sp]), vo = unpack2(ao[sp]);
            float i0 = fast_sigmoid(vi.x), i1 = fast_sigmoid(vi.y);
            float f0 = fast_sigmoid(vf.x), f1 = fast_sigmoid(vf.y);
            float g0 = fast_tanh(vg.x),    g1 = fast_tanh(vg.y);
            float o0 = fast_sigmoid(vo.x), o1 = fast_sigmoid(vo.y);
            c1[2 * sp]     = fmaf(f0, c1[2 * sp],     i0 * g0);
            c1[2 * sp + 1] = fmaf(f1, c1[2 * sp + 1], i1 * g1);
            h1n[2 * sp]     = o0 * fast_tanh(c1[2 * sp]);
            h1n[2 * sp + 1] = o1 * fast_tanh(c1[2 * sp + 1]);
            st->h1[nbuf][sp][lane] = pack2f(h1n[2 * sp], h1n[2 * sp + 1]);
        }
        __syncwarp();  // order h1 stores vs next iteration's cross-lane reads
    }

    // ---- Head (L1 warp only): z = relu(h1 @ W1.T + b1); y = z @ W2.T + b2 ----
    float bias2 = __ldg(b2);
    float bm = (lane < 16) ? __ldg(b1 + lane) : 0.f;
    float w2m = (lane < 16) ? __ldg(W2 + lane) : 0.f;
    float z[8];
#pragma unroll
    for (int ss = 0; ss < 8; ss++) z[ss] = bm;
#pragma unroll
    for (int j = 0; j < H_DIM; j++) {
        float wm = (lane < 16) ? __ldg(W1 + lane * H_DIM + j) : 0.f;
#pragma unroll
        for (int ss = 0; ss < 8; ss++) {
            float hj = __shfl_sync(FULLMASK, h1n[ss], j);
            z[ss] = fmaf(wm, hj, z[ss]);
        }
    }
#pragma unroll
    for (int ss = 0; ss < 8; ss++) {
        float v = fmaxf(z[ss], 0.f) * w2m;
#pragma unroll
        for (int off = 8; off >= 1; off >>= 1)
            v += __shfl_xor_sync(FULLMASK, v, off, 16);
        if (lane == 0) out[seq_base + ss] = v + bias2;
    }
}

extern "C" void kernel_launch(void* const* d_in, const int* in_sizes, int n_in,
                              void* d_out, int out_size) {
    const float* x    = (const float*)d_in[0];
    const float* Wih0 = (const float*)d_in[1];
    const float* Whh0 = (const float*)d_in[2];
    const float* bih0 = (const float*)d_in[3];
    const float* bhh0 = (const float*)d_in[4];
    const float* Wih1 = (const float*)d_in[5];
    const float* Whh1 = (const float*)d_in[6];
    const float* bih1 = (const float*)d_in[7];
    const float* bhh1 = (const float*)d_in[8];
    const float* W1   = (const float*)d_in[9];
    const float* b1   = (const float*)d_in[10];
    const float* W2   = (const float*)d_in[11];
    const float* b2   = (const float*)d_in[12];
    float* out = (float*)d_out;

    int batch = in_sizes[0] / (T_LEN * IN_DIM);  // 4096

    cudaFuncSetAttribute(lstm_fused_kernel,
                         cudaFuncAttributeMaxDynamicSharedMemorySize,
                         (int)sizeof(SmemAll));

    int pairs = (batch + SEQ_PER_PAIR - 1) / SEQ_PER_PAIR;          // 512
    int blocks = (pairs + PAIRS_PER_BLOCK - 1) / PAIRS_PER_BLOCK;   // 128
    lstm_fused_kernel<<<blocks, THREADS, sizeof(SmemAll)>>>(
        x, Wih0, Whh0, bih0, bhh0, Wih1, Whh1, bih1, bhh1,
        W1, b1, W2, b2, out, batch);
}